// round 2
// baseline (speedup 1.0000x reference)
#include <cuda_runtime.h>
#include <cstdint>

// ---------------------------------------------------------------------------
// Problem constants
// ---------------------------------------------------------------------------
#define BATCH   8192
#define CDIM    1024          // d_model * G
#define NPROJ   4096          // (n_head*d_k) * G
#define KPROJ   1024
#define NFC     1024
#define KFC     4096
#define GG      8

// ---------------------------------------------------------------------------
// Device scratch (allocation-free rule: __device__ globals)
// ---------------------------------------------------------------------------
__device__ float g_Wq [4096u * 1024u];   // expanded circulant weights (N x K)
__device__ float g_Wk [4096u * 1024u];
__device__ float g_Wv [4096u * 1024u];
__device__ float g_Wfc[1024u * 4096u];
__device__ float g_Yq [ (size_t)BATCH * 4096u ];  // also reused as Z after attention
__device__ float g_Yk [ (size_t)BATCH * 4096u ];
__device__ float g_Yv [ (size_t)BATCH * 4096u ];
__device__ float g_attn_dummy[(size_t)BATCH * 512u];  // fallback if out_size small

// ---------------------------------------------------------------------------
// Circulant weight expansion:
//   dst[(o*8+g1)*(I*8) + i*8+g2] = src[(o*I + i)*8 + ((g1-g2) & 7)]
// ---------------------------------------------------------------------------
__global__ void expand_kernel(const float* __restrict__ src, float* __restrict__ dst,
                              int O, int I) {
    int total = O * I * 64;
    int KI = I * 8;
    for (int e = blockIdx.x * blockDim.x + threadIdx.x; e < total;
         e += gridDim.x * blockDim.x) {
        int n  = e / KI;
        int kk = e - n * KI;
        int o  = n >> 3, g1 = n & 7;
        int i  = kk >> 3, g2 = kk & 7;
        dst[e] = src[(o * I + i) * 8 + ((g1 - g2) & 7)];
    }
}

// ---------------------------------------------------------------------------
// SGEMM: C[M,N] = A[M,K] * B[N,K]^T (+ bias[n/8]) (+ residual[m,n])
// 128x128 block tile, BK=16, 256 threads, 8x8 per-thread micro-tile
// ---------------------------------------------------------------------------
__global__ __launch_bounds__(256)
void sgemm_nt(const float* __restrict__ A, const float* __restrict__ Bm,
              float* __restrict__ C, int M, int N, int K,
              const float* __restrict__ bias, const float* __restrict__ residual)
{
    __shared__ float As[16][132];
    __shared__ float Bs[16][132];

    int tid = threadIdx.x;
    int tx = tid & 15, ty = tid >> 4;

    const float* Ab = A  + (size_t)blockIdx.y * 128 * K;
    const float* Bb = Bm + (size_t)blockIdx.x * 128 * K;

    float acc[8][8];
#pragma unroll
    for (int i = 0; i < 8; i++)
#pragma unroll
        for (int j = 0; j < 8; j++) acc[i][j] = 0.f;

    int lrow = tid >> 2;          // 0..63
    int lkq  = (tid & 3) * 4;     // 0,4,8,12

    for (int k0 = 0; k0 < K; k0 += 16) {
#pragma unroll
        for (int i = 0; i < 2; i++) {
            int row = lrow + i * 64;
            float4 va = *reinterpret_cast<const float4*>(Ab + (size_t)row * K + k0 + lkq);
            As[lkq + 0][row] = va.x; As[lkq + 1][row] = va.y;
            As[lkq + 2][row] = va.z; As[lkq + 3][row] = va.w;
            float4 vb = *reinterpret_cast<const float4*>(Bb + (size_t)row * K + k0 + lkq);
            Bs[lkq + 0][row] = vb.x; Bs[lkq + 1][row] = vb.y;
            Bs[lkq + 2][row] = vb.z; Bs[lkq + 3][row] = vb.w;
        }
        __syncthreads();
#pragma unroll
        for (int k = 0; k < 16; k++) {
            float4 a0 = *reinterpret_cast<const float4*>(&As[k][ty * 4]);
            float4 a1 = *reinterpret_cast<const float4*>(&As[k][64 + ty * 4]);
            float4 b0 = *reinterpret_cast<const float4*>(&Bs[k][tx * 4]);
            float4 b1 = *reinterpret_cast<const float4*>(&Bs[k][64 + tx * 4]);
            float av[8] = {a0.x, a0.y, a0.z, a0.w, a1.x, a1.y, a1.z, a1.w};
            float bv[8] = {b0.x, b0.y, b0.z, b0.w, b1.x, b1.y, b1.z, b1.w};
#pragma unroll
            for (int i = 0; i < 8; i++)
#pragma unroll
                for (int j = 0; j < 8; j++)
                    acc[i][j] = fmaf(av[i], bv[j], acc[i][j]);
        }
        __syncthreads();
    }

#pragma unroll
    for (int i = 0; i < 8; i++) {
        int r = blockIdx.y * 128 + ((i < 4) ? (ty * 4 + i) : (64 + ty * 4 + (i - 4)));
#pragma unroll
        for (int j = 0; j < 8; j++) {
            int c = blockIdx.x * 128 + ((j < 4) ? (tx * 4 + j) : (64 + tx * 4 + (j - 4)));
            float val = acc[i][j];
            if (bias)     val += bias[c >> 3];
            if (residual) val += residual[(size_t)r * N + c];
            C[(size_t)r * N + c] = val;
        }
    }
}

// ---------------------------------------------------------------------------
// Per-batch attention: 8 heads, seq-len 8, dim 64.
// Row layout within y[b]: idx = g*512 + h*64 + d  (same for inputs and Z).
// One block per batch element; warp w handles head w.
// smem rows padded to 516 floats so the stride-512 gathers are conflict-free.
// ---------------------------------------------------------------------------
#define ROWSTR 516   // floats; 516 % 32 == 4 -> 8 distinct banks for g in 0..7

__global__ __launch_bounds__(256)
void attn_kernel(const float* Yq, const float* __restrict__ Yk,
                 const float* __restrict__ Yv, float* Z,
                 float* __restrict__ attn_out)
{
    extern __shared__ float sm[];
    float* sQ = sm;
    float* sK = sm + 8 * ROWSTR;
    float* sV = sm + 16 * ROWSTR;

    int b   = blockIdx.x;
    int tid = threadIdx.x;

    const float4* q4 = (const float4*)(Yq + (size_t)b * 4096);
    const float4* k4 = (const float4*)(Yk + (size_t)b * 4096);
    const float4* v4 = (const float4*)(Yv + (size_t)b * 4096);
    for (int i = tid; i < 1024; i += 256) {
        int gg  = i >> 7;           // row (0..7), 128 float4 per row
        int off = i & 127;
        int d4  = gg * (ROWSTR / 4) + off;
        ((float4*)sQ)[d4] = q4[i];
        ((float4*)sK)[d4] = k4[i];
        ((float4*)sV)[d4] = v4[i];
    }
    __syncthreads();

    int w    = tid >> 5;
    int lane = tid & 31;
    int base = w * 64;
    int g1a  = lane >> 3;       // 0..3
    int g2   = lane & 7;
    int g1b  = g1a + 4;

    // scores: s[g1][g2] = (q[g1] . k[g2]) / sqrt(64)
    const float* qa = sQ + g1a * ROWSTR + base;
    const float* qb = sQ + g1b * ROWSTR + base;
    const float* kr = sK + g2  * ROWSTR + base;
    float s0 = 0.f, s1 = 0.f;
#pragma unroll 8
    for (int d = 0; d < 64; d++) {
        float kv = kr[d];
        s0 = fmaf(qa[d], kv, s0);
        s1 = fmaf(qb[d], kv, s1);
    }
    s0 *= 0.125f; s1 *= 0.125f;

    // softmax over g2 (groups of 8 contiguous lanes)
    float m0 = s0, m1 = s1;
#pragma unroll
    for (int off = 4; off; off >>= 1) {
        m0 = fmaxf(m0, __shfl_xor_sync(0xffffffffu, m0, off));
        m1 = fmaxf(m1, __shfl_xor_sync(0xffffffffu, m1, off));
    }
    float e0 = __expf(s0 - m0), e1 = __expf(s1 - m1);
    float z0 = e0, z1 = e1;
#pragma unroll
    for (int off = 4; off; off >>= 1) {
        z0 += __shfl_xor_sync(0xffffffffu, z0, off);
        z1 += __shfl_xor_sync(0xffffffffu, z1, off);
    }
    float a0 = e0 / z0, a1 = e1 / z1;

    // attn[b, h, g1, g2] -> offset b*512 + h*64 + g1*8 + g2
    attn_out[(size_t)b * 512 + base + lane]      = a0;
    attn_out[(size_t)b * 512 + base + 32 + lane] = a1;

    __syncwarp();
    // stash attn weights into (now-dead for this warp's columns) sQ
    sQ[g1a * ROWSTR + base + g2] = a0;
    sQ[g1b * ROWSTR + base + g2] = a1;
    __syncwarp();

    // out[g1][d] = sum_g2 attn[g1][g2] * v[g2][d]; Z row layout == y layout
    float* zrow = Z + (size_t)b * 4096 + base;
#pragma unroll
    for (int g1 = 0; g1 < 8; g1++) {
        const float* ar = sQ + g1 * ROWSTR + base;
        float acc0 = 0.f, acc1 = 0.f;
#pragma unroll
        for (int j = 0; j < 8; j++) {
            float a = ar[j];
            acc0 = fmaf(a, sV[j * ROWSTR + base + lane],      acc0);
            acc1 = fmaf(a, sV[j * ROWSTR + base + 32 + lane], acc1);
        }
        zrow[g1 * 512 + lane]      = acc0;
        zrow[g1 * 512 + 32 + lane] = acc1;
    }
}

// ---------------------------------------------------------------------------
// Launch
// ---------------------------------------------------------------------------
extern "C" void kernel_launch(void* const* d_in, const int* in_sizes, int n_in,
                              void* d_out, int out_size) {
    const float* q    = (const float*)d_in[0];
    const float* k    = (const float*)d_in[1];
    const float* v    = (const float*)d_in[2];
    const float* w_q  = (const float*)d_in[3];
    const float* b_q  = (const float*)d_in[4];
    const float* w_k  = (const float*)d_in[5];
    const float* b_k  = (const float*)d_in[6];
    const float* w_v  = (const float*)d_in[7];
    const float* b_v  = (const float*)d_in[8];
    const float* w_fc = (const float*)d_in[9];
    const float* b_fc = (const float*)d_in[10];

    float* out = (float*)d_out;
    const size_t OUT_ELEMS  = (size_t)BATCH * CDIM;         // 8,388,608
    const size_t ATTN_ELEMS = (size_t)BATCH * 512;          // 4,194,304

    float *Wq, *Wk, *Wv, *Wfc, *Yq, *Yk, *Yv, *attnDummy;
    cudaGetSymbolAddress((void**)&Wq,  g_Wq);
    cudaGetSymbolAddress((void**)&Wk,  g_Wk);
    cudaGetSymbolAddress((void**)&Wv,  g_Wv);
    cudaGetSymbolAddress((void**)&Wfc, g_Wfc);
    cudaGetSymbolAddress((void**)&Yq,  g_Yq);
    cudaGetSymbolAddress((void**)&Yk,  g_Yk);
    cudaGetSymbolAddress((void**)&Yv,  g_Yv);
    cudaGetSymbolAddress((void**)&attnDummy, g_attn_dummy);

    float* attn_out = ((size_t)out_size >= OUT_ELEMS + ATTN_ELEMS)
                          ? (out + OUT_ELEMS) : attnDummy;

    // 1) expand circulant weights
    expand_kernel<<<2048, 256>>>(w_q,  Wq,  512, 128);
    expand_kernel<<<2048, 256>>>(w_k,  Wk,  512, 128);
    expand_kernel<<<2048, 256>>>(w_v,  Wv,  512, 128);
    expand_kernel<<<2048, 256>>>(w_fc, Wfc, 128, 512);

    // 2) q/k/v projections: [8192,1024] x [4096,1024]^T
    dim3 gp(NPROJ / 128, BATCH / 128);
    sgemm_nt<<<gp, 256>>>(q, Wq, Yq, BATCH, NPROJ, KPROJ, b_q, nullptr);
    sgemm_nt<<<gp, 256>>>(k, Wk, Yk, BATCH, NPROJ, KPROJ, b_k, nullptr);
    sgemm_nt<<<gp, 256>>>(v, Wv, Yv, BATCH, NPROJ, KPROJ, b_v, nullptr);

    // 3) attention (Z aliases Yq; each block stages its own row first)
    static const int attn_smem = 24 * ROWSTR * (int)sizeof(float);  // 49,536 B
    cudaFuncSetAttribute(attn_kernel, cudaFuncAttributeMaxDynamicSharedMemorySize,
                         attn_smem);
    attn_kernel<<<BATCH, 256, attn_smem>>>(Yq, Yk, Yv, Yq, attn_out);

    // 4) fc projection + bias + residual: [8192,4096] x [1024,4096]^T
    dim3 gf(NFC / 128, BATCH / 128);
    sgemm_nt<<<gf, 256>>>(Yq, Wfc, out, BATCH, NFC, KFC, b_fc, q);
}

// round 5
// speedup vs baseline: 2.1617x; 2.1617x over previous
#include <cuda_runtime.h>
#include <cuda_bf16.h>
#include <cstdint>

// ---------------------------------------------------------------------------
// Problem constants
// ---------------------------------------------------------------------------
#define BATCH   8192
#define CDIM    1024
#define NPROJ   4096
#define KPROJ   1024
#define NFC     1024
#define KFC     4096

// ---------------------------------------------------------------------------
// Device scratch
// ---------------------------------------------------------------------------
__device__ float g_Wq [4096u * 1024u];
__device__ float g_Wk [4096u * 1024u];
__device__ float g_Wv [4096u * 1024u];
__device__ float g_Wfc[1024u * 4096u];
__device__ float g_Yq [(size_t)BATCH * 4096u];   // reused as Z after attention
__device__ float g_Yk [(size_t)BATCH * 4096u];
__device__ float g_Yv [(size_t)BATCH * 4096u];
__device__ float g_attn_dummy[(size_t)BATCH * 512u];

// ---------------------------------------------------------------------------
// Circulant weight expansion
// ---------------------------------------------------------------------------
__global__ void expand_kernel(const float* __restrict__ src, float* __restrict__ dst,
                              int O, int I, int sh) {
    int total = O * I * 64;
    int mask = I * 8 - 1;
    for (int e = blockIdx.x * blockDim.x + threadIdx.x; e < total;
         e += gridDim.x * blockDim.x) {
        int n  = e >> sh;
        int kk = e & mask;
        int o  = n >> 3, g1 = n & 7;
        int i  = kk >> 3, g2 = kk & 7;
        dst[e] = src[(o * I + i) * 8 + ((g1 - g2) & 7)];
    }
}

// ---------------------------------------------------------------------------
// bf16 split-2, 3-pass tensor-core GEMM:
//   C[M,N] = A[M,K] * B[N,K]^T (+ bias[n/8]) (+ residual)
// 128x128 block tile, BK=32, 256 threads (8 warps, 2x4), warp tile 64x32.
// mma.sync.m16n8k16 bf16 with fp32 accumulators (sm_80-baseline PTX).
// ---------------------------------------------------------------------------
#define TM 128
#define TN 128
#define TK 32
#define PADK 40                       // halves per smem row (conflict-free)
#define TILE_H (128 * PADK)           // halves per tile  (5120)
#define STAGE_H (4 * TILE_H)          // halves per stage (20480)
#define GEMM_SMEM_BYTES (2 * STAGE_H * 2)   // 81,920 B

__device__ __forceinline__ void mma16816(float* c, const uint32_t* a, const uint32_t* b) {
    asm volatile(
        "mma.sync.aligned.m16n8k16.row.col.f32.bf16.bf16.f32 "
        "{%0,%1,%2,%3}, {%4,%5,%6,%7}, {%8,%9}, {%0,%1,%2,%3};"
        : "+f"(c[0]), "+f"(c[1]), "+f"(c[2]), "+f"(c[3])
        : "r"(a[0]), "r"(a[1]), "r"(a[2]), "r"(a[3]), "r"(b[0]), "r"(b[1]));
}

// split fp32x4 -> bf16 hi (truncate) + bf16 lo (rn of exact residual), store
__device__ __forceinline__ void split_sts(float4 v, uint16_t* ph, uint16_t* pl) {
    uint32_t ux = __float_as_uint(v.x), uy = __float_as_uint(v.y);
    uint32_t uz = __float_as_uint(v.z), uw = __float_as_uint(v.w);
    uint32_t h0 = __byte_perm(ux, uy, 0x7632);
    uint32_t h1 = __byte_perm(uz, uw, 0x7632);
    float lx = v.x - __uint_as_float(ux & 0xffff0000u);
    float ly = v.y - __uint_as_float(uy & 0xffff0000u);
    float lz = v.z - __uint_as_float(uz & 0xffff0000u);
    float lw = v.w - __uint_as_float(uw & 0xffff0000u);
    uint32_t l0, l1;
    asm("cvt.rn.bf16x2.f32 %0, %1, %2;" : "=r"(l0) : "f"(ly), "f"(lx));
    asm("cvt.rn.bf16x2.f32 %0, %1, %2;" : "=r"(l1) : "f"(lw), "f"(lz));
    uint2 hv; hv.x = h0; hv.y = h1;
    uint2 lv; lv.x = l0; lv.y = l1;
    *reinterpret_cast<uint2*>(ph) = hv;
    *reinterpret_cast<uint2*>(pl) = lv;
}

__global__ __launch_bounds__(256)
void gemm_bf16x3(const float* __restrict__ A, const float* __restrict__ B,
                 float* __restrict__ C, int N, int K,
                 const float* __restrict__ bias, const float* __restrict__ residual)
{
    extern __shared__ uint16_t sm16[];

    const int tid  = threadIdx.x;
    const int wid  = tid >> 5, lane = tid & 31;
    const int wm   = wid >> 2, wn = wid & 3;       // warp tile (wm*64, wn*32)
    const int q    = lane >> 2;                    // 0..7
    const int t4   = (lane & 3) * 2;               // 0,2,4,6

    const size_t m0 = (size_t)blockIdx.y * TM;
    const size_t n0 = (size_t)blockIdx.x * TN;
    const float* Ab = A + m0 * K;
    const float* Bb = B + n0 * K;

    float acc[4][4][4];
#pragma unroll
    for (int i = 0; i < 4; i++)
#pragma unroll
        for (int j = 0; j < 4; j++)
#pragma unroll
            for (int r = 0; r < 4; r++) acc[i][j][r] = 0.f;

    // per-thread load geometry: 4 float4 per tile (1024 float4 / 256 thr)
    float4 ra[4], rb[4];
#pragma unroll
    for (int i = 0; i < 4; i++) {
        int e = tid + i * 256, row = e >> 3, k4 = (e & 7) * 4;
        ra[i] = *reinterpret_cast<const float4*>(Ab + (size_t)row * K + k4);
        rb[i] = *reinterpret_cast<const float4*>(Bb + (size_t)row * K + k4);
    }

    const int NC = K / TK;
    for (int c = 0; c < NC; c++) {
        const int s = c & 1;
        uint16_t* Ah = sm16 + s * STAGE_H;
        uint16_t* Al = Ah + TILE_H;
        uint16_t* Bh = Ah + 2 * TILE_H;
        uint16_t* Bl = Ah + 3 * TILE_H;

        // ---- convert + store current chunk
#pragma unroll
        for (int i = 0; i < 4; i++) {
            int e = tid + i * 256, row = e >> 3, k4 = (e & 7) * 4;
            int off = row * PADK + k4;
            split_sts(ra[i], Ah + off, Al + off);
            split_sts(rb[i], Bh + off, Bl + off);
        }
        __syncthreads();

        // ---- prefetch next chunk (overlaps with MMA below)
        if (c + 1 < NC) {
            int k0 = (c + 1) * TK;
#pragma unroll
            for (int i = 0; i < 4; i++) {
                int e = tid + i * 256, row = e >> 3, k4 = (e & 7) * 4;
                ra[i] = *reinterpret_cast<const float4*>(Ab + (size_t)row * K + k0 + k4);
                rb[i] = *reinterpret_cast<const float4*>(Bb + (size_t)row * K + k0 + k4);
            }
        }

        // ---- compute: 2 k-steps x (16 frags x 3 passes)
#pragma unroll
        for (int ks = 0; ks < 2; ks++) {
            const int kb = ks * 16;
            uint32_t ah[4][4], al[4][4], bh[4][2], bl[4][2];
#pragma unroll
            for (int i = 0; i < 4; i++) {
                int r = wm * 64 + i * 16 + q;
                int o00 = r * PADK + kb + t4;
                int o10 = (r + 8) * PADK + kb + t4;
                ah[i][0] = *reinterpret_cast<const uint32_t*>(Ah + o00);
                ah[i][1] = *reinterpret_cast<const uint32_t*>(Ah + o10);
                ah[i][2] = *reinterpret_cast<const uint32_t*>(Ah + o00 + 8);
                ah[i][3] = *reinterpret_cast<const uint32_t*>(Ah + o10 + 8);
                al[i][0] = *reinterpret_cast<const uint32_t*>(Al + o00);
                al[i][1] = *reinterpret_cast<const uint32_t*>(Al + o10);
                al[i][2] = *reinterpret_cast<const uint32_t*>(Al + o00 + 8);
                al[i][3] = *reinterpret_cast<const uint32_t*>(Al + o10 + 8);
            }
#pragma unroll
            for (int j = 0; j < 4; j++) {
                int r = wn * 32 + j * 8 + q;
                int o0 = r * PADK + kb + t4;
                bh[j][0] = *reinterpret_cast<const uint32_t*>(Bh + o0);
                bh[j][1] = *reinterpret_cast<const uint32_t*>(Bh + o0 + 8);
                bl[j][0] = *reinterpret_cast<const uint32_t*>(Bl + o0);
                bl[j][1] = *reinterpret_cast<const uint32_t*>(Bl + o0 + 8);
            }
            // pass 1: ah*bh ; pass 2: al*bh ; pass 3: ah*bl
#pragma unroll
            for (int i = 0; i < 4; i++)
#pragma unroll
                for (int j = 0; j < 4; j++) mma16816(acc[i][j], ah[i], bh[j]);
#pragma unroll
            for (int i = 0; i < 4; i++)
#pragma unroll
                for (int j = 0; j < 4; j++) mma16816(acc[i][j], al[i], bh[j]);
#pragma unroll
            for (int i = 0; i < 4; i++)
#pragma unroll
                for (int j = 0; j < 4; j++) mma16816(acc[i][j], ah[i], bl[j]);
        }
        __syncthreads();
    }

    // ---- epilogue: bias (+residual), direct STG from fragments
#pragma unroll
    for (int i = 0; i < 4; i++) {
        size_t r = m0 + wm * 64 + i * 16 + q;
#pragma unroll
        for (int j = 0; j < 4; j++) {
            size_t col = n0 + wn * 32 + j * 8 + t4;
            float bv = bias[col >> 3];
            float2 v0, v1;
            v0.x = acc[i][j][0] + bv; v0.y = acc[i][j][1] + bv;
            v1.x = acc[i][j][2] + bv; v1.y = acc[i][j][3] + bv;
            if (residual) {
                float2 r0 = *reinterpret_cast<const float2*>(residual + r * N + col);
                float2 r1 = *reinterpret_cast<const float2*>(residual + (r + 8) * N + col);
                v0.x += r0.x; v0.y += r0.y;
                v1.x += r1.x; v1.y += r1.y;
            }
            *reinterpret_cast<float2*>(C + r * N + col)       = v0;
            *reinterpret_cast<float2*>(C + (r + 8) * N + col) = v1;
        }
    }
}

// ---------------------------------------------------------------------------
// Per-batch attention: 8 heads, seq-len 8, dim 64.  (proven in round 2)
// ---------------------------------------------------------------------------
#define ROWSTR 516

__global__ __launch_bounds__(256)
void attn_kernel(const float* Yq, const float* __restrict__ Yk,
                 const float* __restrict__ Yv, float* Z,
                 float* __restrict__ attn_out)
{
    extern __shared__ float sm[];
    float* sQ = sm;
    float* sK = sm + 8 * ROWSTR;
    float* sV = sm + 16 * ROWSTR;

    int b   = blockIdx.x;
    int tid = threadIdx.x;

    const float4* q4 = (const float4*)(Yq + (size_t)b * 4096);
    const float4* k4 = (const float4*)(Yk + (size_t)b * 4096);
    const float4* v4 = (const float4*)(Yv + (size_t)b * 4096);
    for (int i = tid; i < 1024; i += 256) {
        int gg  = i >> 7;
        int off = i & 127;
        int d4  = gg * (ROWSTR / 4) + off;
        ((float4*)sQ)[d4] = q4[i];
        ((float4*)sK)[d4] = k4[i];
        ((float4*)sV)[d4] = v4[i];
    }
    __syncthreads();

    int w    = tid >> 5;
    int lane = tid & 31;
    int base = w * 64;
    int g1a  = lane >> 3;
    int g2   = lane & 7;
    int g1b  = g1a + 4;

    const float* qa = sQ + g1a * ROWSTR + base;
    const float* qb = sQ + g1b * ROWSTR + base;
    const float* kr = sK + g2  * ROWSTR + base;
    float s0 = 0.f, s1 = 0.f;
#pragma unroll 8
    for (int d = 0; d < 64; d++) {
        float kv = kr[d];
        s0 = fmaf(qa[d], kv, s0);
        s1 = fmaf(qb[d], kv, s1);
    }
    s0 *= 0.125f; s1 *= 0.125f;

    float m0 = s0, m1 = s1;
#pragma unroll
    for (int off = 4; off; off >>= 1) {
        m0 = fmaxf(m0, __shfl_xor_sync(0xffffffffu, m0, off));
        m1 = fmaxf(m1, __shfl_xor_sync(0xffffffffu, m1, off));
    }
    float e0 = __expf(s0 - m0), e1 = __expf(s1 - m1);
    float z0 = e0, z1 = e1;
#pragma unroll
    for (int off = 4; off; off >>= 1) {
        z0 += __shfl_xor_sync(0xffffffffu, z0, off);
        z1 += __shfl_xor_sync(0xffffffffu, z1, off);
    }
    float a0 = e0 / z0, a1 = e1 / z1;

    attn_out[(size_t)b * 512 + base + lane]      = a0;
    attn_out[(size_t)b * 512 + base + 32 + lane] = a1;

    __syncwarp();
    sQ[g1a * ROWSTR + base + g2] = a0;
    sQ[g1b * ROWSTR + base + g2] = a1;
    __syncwarp();

    float* zrow = Z + (size_t)b * 4096 + base;
#pragma unroll
    for (int g1 = 0; g1 < 8; g1++) {
        const float* ar = sQ + g1 * ROWSTR + base;
        float acc0 = 0.f, acc1 = 0.f;
#pragma unroll
        for (int j = 0; j < 8; j++) {
            float a = ar[j];
            acc0 = fmaf(a, sV[j * ROWSTR + base + lane],      acc0);
            acc1 = fmaf(a, sV[j * ROWSTR + base + 32 + lane], acc1);
        }
        zrow[g1 * 512 + lane]      = acc0;
        zrow[g1 * 512 + 32 + lane] = acc1;
    }
}

// ---------------------------------------------------------------------------
// Launch
// ---------------------------------------------------------------------------
extern "C" void kernel_launch(void* const* d_in, const int* in_sizes, int n_in,
                              void* d_out, int out_size) {
    const float* q    = (const float*)d_in[0];
    const float* k    = (const float*)d_in[1];
    const float* v    = (const float*)d_in[2];
    const float* w_q  = (const float*)d_in[3];
    const float* b_q  = (const float*)d_in[4];
    const float* w_k  = (const float*)d_in[5];
    const float* b_k  = (const float*)d_in[6];
    const float* w_v  = (const float*)d_in[7];
    const float* b_v  = (const float*)d_in[8];
    const float* w_fc = (const float*)d_in[9];
    const float* b_fc = (const float*)d_in[10];

    float* out = (float*)d_out;
    const size_t OUT_ELEMS  = (size_t)BATCH * CDIM;
    const size_t ATTN_ELEMS = (size_t)BATCH * 512;

    float *Wq, *Wk, *Wv, *Wfc, *Yq, *Yk, *Yv, *attnDummy;
    cudaGetSymbolAddress((void**)&Wq,  g_Wq);
    cudaGetSymbolAddress((void**)&Wk,  g_Wk);
    cudaGetSymbolAddress((void**)&Wv,  g_Wv);
    cudaGetSymbolAddress((void**)&Wfc, g_Wfc);
    cudaGetSymbolAddress((void**)&Yq,  g_Yq);
    cudaGetSymbolAddress((void**)&Yk,  g_Yk);
    cudaGetSymbolAddress((void**)&Yv,  g_Yv);
    cudaGetSymbolAddress((void**)&attnDummy, g_attn_dummy);

    float* attn_out = ((size_t)out_size >= OUT_ELEMS + ATTN_ELEMS)
                          ? (out + OUT_ELEMS) : attnDummy;

    // 1) expand circulant weights
    expand_kernel<<<2048, 256>>>(w_q,  Wq,  512, 128, 10);
    expand_kernel<<<2048, 256>>>(w_k,  Wk,  512, 128, 10);
    expand_kernel<<<2048, 256>>>(w_v,  Wv,  512, 128, 10);
    expand_kernel<<<2048, 256>>>(w_fc, Wfc, 128, 512, 12);

    // 2) q/k/v projections (bf16 split-2, 3-pass tensor-core GEMM)
    cudaFuncSetAttribute(gemm_bf16x3, cudaFuncAttributeMaxDynamicSharedMemorySize,
                         GEMM_SMEM_BYTES);
    dim3 gp(NPROJ / TN, BATCH / TM);           // (32, 64)
    gemm_bf16x3<<<gp, 256, GEMM_SMEM_BYTES>>>(q, Wq, Yq, NPROJ, KPROJ, b_q, nullptr);
    gemm_bf16x3<<<gp, 256, GEMM_SMEM_BYTES>>>(k, Wk, Yk, NPROJ, KPROJ, b_k, nullptr);
    gemm_bf16x3<<<gp, 256, GEMM_SMEM_BYTES>>>(v, Wv, Yv, NPROJ, KPROJ, b_v, nullptr);

    // 3) attention (Z aliases Yq)
    static const int attn_smem = 24 * ROWSTR * (int)sizeof(float);
    cudaFuncSetAttribute(attn_kernel, cudaFuncAttributeMaxDynamicSharedMemorySize,
                         attn_smem);
    attn_kernel<<<BATCH, 256, attn_smem>>>(Yq, Yk, Yv, Yq, attn_out);

    // 4) fc projection + bias + residual
    dim3 gf(NFC / TN, BATCH / TM);             // (8, 64)
    gemm_bf16x3<<<gf, 256, GEMM_SMEM_BYTES>>>(Yq, Wfc, out, NFC, KFC, b_fc, q);
}